// round 5
// baseline (speedup 1.0000x reference)
#include <cuda_runtime.h>
#include <cuda_bf16.h>
#include <cstdint>

// ResiduePooling: scatter_mean(atom_features[2e6,128], residue_index(sorted) -> [250000,128])
//
// Pass 1: build segment start offsets from the sorted index (vectorized: one
//         thread per 4 indices, wide loads). Index dtype (int64 vs int32)
//         detected inline from uniform probe loads.
// Pass 2: one warp per 4 CONSECUTIVE residues (their atom ranges are
//         contiguous since the index is sorted) -> one long contiguous
//         512B-per-row stream per warp, amortizing the dependent
//         offset-load/address-setup prologue 4x. Lane owns one float4 of the
//         128-wide row. Evict-streaming hints (zero reuse). Empty residues
//         write 0 (== 0/max(cnt,1)).

#define NUM_RESIDUES 250000
#define FEAT_DIM 128
#define R_PER_WARP 4   // NUM_RESIDUES % R_PER_WARP == 0

__device__ int g_seg_start[NUM_RESIDUES + 1];

__device__ __forceinline__ bool detect_is64(const int* __restrict__ v, int n) {
    // Safe region: first n int32 slots exist for both dtypes.
    // int64 little-endian values < 2^31: every odd int32 slot is zero.
    int p0 = __ldg(v + 1);
    int p1 = __ldg(v + ((n > 1002) ? 1001 : 1));
    int p2 = __ldg(v + ((n > 100002) ? 100001 : 1));
    int p3 = __ldg(v + (n - 1));
    return ((p0 | p1 | p2 | p3) == 0);
}

__global__ void __launch_bounds__(256) build_offsets_kernel(const void* __restrict__ idxv, int n) {
    const bool is64 = detect_is64((const int*)idxv, n);

    int t = blockIdx.x * blockDim.x + threadIdx.x;
    int base = t * 4;
    if (base >= n) return;

    int r[4];
    int nvalid = (n - base >= 4) ? 4 : (n - base);

    if (is64) {
        const long long* __restrict__ p = (const long long*)idxv;
        if (nvalid == 4) {
            ulonglong2 v0 = *(const ulonglong2*)(p + base);
            ulonglong2 v1 = *(const ulonglong2*)(p + base + 2);
            r[0] = (int)v0.x; r[1] = (int)v0.y; r[2] = (int)v1.x; r[3] = (int)v1.y;
        } else {
            for (int j = 0; j < nvalid; j++) r[j] = (int)p[base + j];
        }
    } else {
        const int* __restrict__ p = (const int*)idxv;
        if (nvalid == 4) {
            int4 v = *(const int4*)(p + base);
            r[0] = v.x; r[1] = v.y; r[2] = v.z; r[3] = v.w;
        } else {
            for (int j = 0; j < nvalid; j++) r[j] = p[base + j];
        }
    }

    int prev;
    if (base == 0) {
        prev = -1;
    } else {
        prev = is64 ? (int)((const long long*)idxv)[base - 1]
                    : ((const int*)idxv)[base - 1];
    }

    #pragma unroll
    for (int j = 0; j < 4; j++) {
        if (j < nvalid) {
            int rj = r[j];
            for (int q = prev + 1; q <= rj; q++) g_seg_start[q] = base + j;
            prev = rj;
        }
    }

    if (base + nvalid == n) {
        for (int q = prev + 1; q <= NUM_RESIDUES; q++) g_seg_start[q] = n;
    }
}

__global__ void __launch_bounds__(64) pool_kernel(const float* __restrict__ feat,
                                                  float* __restrict__ out) {
    int gwarp = (blockIdx.x * blockDim.x + threadIdx.x) >> 5;
    int lane  = threadIdx.x & 31;
    int r0 = gwarp * R_PER_WARP;
    if (r0 >= NUM_RESIDUES) return;

    // Lanes 0..R_PER_WARP load the 5 consecutive boundaries; broadcast.
    int b = 0;
    if (lane <= R_PER_WARP) b = __ldg(&g_seg_start[r0 + lane]);
    int seg[R_PER_WARP + 1];
    #pragma unroll
    for (int k = 0; k <= R_PER_WARP; k++) seg[k] = __shfl_sync(0xffffffff, b, k);

    // Streaming pointer: contiguous across the 4 segments.
    const float4* __restrict__ p = (const float4*)(feat + (size_t)seg[0] * FEAT_DIM) + lane;
    float4* __restrict__ orow = (float4*)(out + (size_t)r0 * FEAT_DIM) + lane;

    #pragma unroll
    for (int k = 0; k < R_PER_WARP; k++) {
        int cnt = seg[k + 1] - seg[k];

        float4 acc0 = make_float4(0.f, 0.f, 0.f, 0.f);
        float4 acc1 = make_float4(0.f, 0.f, 0.f, 0.f);

        int a = 0;
        for (; a + 4 <= cnt; a += 4) {
            float4 v0 = __ldcs(p);
            float4 v1 = __ldcs(p + 32);
            float4 v2 = __ldcs(p + 64);
            float4 v3 = __ldcs(p + 96);
            p += 128;
            acc0.x += v0.x; acc0.y += v0.y; acc0.z += v0.z; acc0.w += v0.w;
            acc1.x += v1.x; acc1.y += v1.y; acc1.z += v1.z; acc1.w += v1.w;
            acc0.x += v2.x; acc0.y += v2.y; acc0.z += v2.z; acc0.w += v2.w;
            acc1.x += v3.x; acc1.y += v3.y; acc1.z += v3.z; acc1.w += v3.w;
        }
        if (a + 2 <= cnt) {
            float4 v0 = __ldcs(p);
            float4 v1 = __ldcs(p + 32);
            p += 64;
            a += 2;
            acc0.x += v0.x; acc0.y += v0.y; acc0.z += v0.z; acc0.w += v0.w;
            acc1.x += v1.x; acc1.y += v1.y; acc1.z += v1.z; acc1.w += v1.w;
        }
        if (a < cnt) {
            float4 v0 = __ldcs(p);
            p += 32;
            acc0.x += v0.x; acc0.y += v0.y; acc0.z += v0.z; acc0.w += v0.w;
        }

        float inv = (cnt > 0) ? (1.0f / (float)cnt) : 0.0f;
        float4 r;
        r.x = (acc0.x + acc1.x) * inv;
        r.y = (acc0.y + acc1.y) * inv;
        r.z = (acc0.z + acc1.z) * inv;
        r.w = (acc0.w + acc1.w) * inv;

        __stcs(orow, r);
        orow += 32;  // next output row (128 floats)
    }
}

extern "C" void kernel_launch(void* const* d_in, const int* in_sizes, int n_in,
                              void* d_out, int out_size) {
    const float* feat = (const float*)d_in[0];
    const void* idx   = (const void*)d_in[1];
    int n_atoms       = in_sizes[1];

    int elems_per_thread = 4;
    int threads = 256;
    int work = (n_atoms + elems_per_thread - 1) / elems_per_thread;
    int blocks = (work + threads - 1) / threads;
    build_offsets_kernel<<<blocks, threads>>>(idx, n_atoms);

    // One warp per 4 residues; 2 warps per block.
    int total_warps = NUM_RESIDUES / R_PER_WARP;           // 62500
    int warps_per_block = 2;
    int pool_blocks = (total_warps + warps_per_block - 1) / warps_per_block;
    pool_kernel<<<pool_blocks, warps_per_block * 32>>>(feat, (float*)d_out);
}

// round 6
// speedup vs baseline: 1.0339x; 1.0339x over previous
#include <cuda_runtime.h>
#include <cuda_bf16.h>
#include <cstdint>

// ResiduePooling: scatter_mean(atom_features[2e6,128], residue_index(sorted) -> [250000,128])
//
// Pass 1: build segment start offsets from the sorted index (one thread per 8
//         indices, wide contiguous loads). Index dtype (int64 vs int32)
//         detected inline from uniform probe loads.
// Pass 2: one warp per residue, 64-thread blocks (2 warps) to minimize
//         intra-block tail skew. Each lane owns one float4 of the 128-wide
//         feature row; streams the segment with coalesced 512B LDG.128 bursts
//         (evict-streaming), scales by 1/count, writes one coalesced 512B row.
//         Empty residues write 0 (== 0/max(cnt,1)).

#define NUM_RESIDUES 250000
#define FEAT_DIM 128
#define IDX_PER_THREAD 8

__device__ int g_seg_start[NUM_RESIDUES + 1];

__device__ __forceinline__ bool detect_is64(const int* __restrict__ v, int n) {
    // Safe region: first n int32 slots exist for both dtypes.
    // int64 little-endian values < 2^31: every odd int32 slot is zero.
    int p0 = __ldg(v + 1);
    int p1 = __ldg(v + ((n > 1002) ? 1001 : 1));
    int p2 = __ldg(v + ((n > 100002) ? 100001 : 1));
    int p3 = __ldg(v + (n - 1));
    return ((p0 | p1 | p2 | p3) == 0);
}

__global__ void __launch_bounds__(256) build_offsets_kernel(const void* __restrict__ idxv, int n) {
    const bool is64 = detect_is64((const int*)idxv, n);

    int t = blockIdx.x * blockDim.x + threadIdx.x;
    int base = t * IDX_PER_THREAD;
    if (base >= n) return;

    int nvalid = (n - base >= IDX_PER_THREAD) ? IDX_PER_THREAD : (n - base);
    int r[IDX_PER_THREAD];

    if (is64) {
        const long long* __restrict__ p = (const long long*)idxv;
        if (nvalid == IDX_PER_THREAD) {
            // 4 x 16B contiguous loads (64B per thread, 2KB per warp).
            #pragma unroll
            for (int j = 0; j < IDX_PER_THREAD / 2; j++) {
                ulonglong2 v = *(const ulonglong2*)(p + base + 2 * j);
                r[2 * j]     = (int)v.x;
                r[2 * j + 1] = (int)v.y;
            }
        } else {
            for (int j = 0; j < nvalid; j++) r[j] = (int)p[base + j];
        }
    } else {
        const int* __restrict__ p = (const int*)idxv;
        if (nvalid == IDX_PER_THREAD) {
            #pragma unroll
            for (int j = 0; j < IDX_PER_THREAD / 4; j++) {
                int4 v = *(const int4*)(p + base + 4 * j);
                r[4 * j]     = v.x;
                r[4 * j + 1] = v.y;
                r[4 * j + 2] = v.z;
                r[4 * j + 3] = v.w;
            }
        } else {
            for (int j = 0; j < nvalid; j++) r[j] = p[base + j];
        }
    }

    int prev;
    if (base == 0) {
        prev = -1;
    } else {
        prev = is64 ? (int)((const long long*)idxv)[base - 1]
                    : ((const int*)idxv)[base - 1];
    }

    #pragma unroll
    for (int j = 0; j < IDX_PER_THREAD; j++) {
        if (j < nvalid) {
            int rj = r[j];
            for (int q = prev + 1; q <= rj; q++) g_seg_start[q] = base + j;
            prev = rj;
        }
    }

    if (base + nvalid == n) {
        for (int q = prev + 1; q <= NUM_RESIDUES; q++) g_seg_start[q] = n;
    }
}

__global__ void __launch_bounds__(64) pool_kernel(const float* __restrict__ feat,
                                                  float* __restrict__ out) {
    int gwarp = (blockIdx.x * blockDim.x + threadIdx.x) >> 5;  // residue id
    int lane  = threadIdx.x & 31;
    if (gwarp >= NUM_RESIDUES) return;

    int s = __ldg(&g_seg_start[gwarp]);
    int e = __ldg(&g_seg_start[gwarp + 1]);
    int cnt = e - s;

    // Per-row stride in float4 units = 128/4 = 32.
    const float4* __restrict__ p = (const float4*)(feat + (size_t)s * FEAT_DIM) + lane;

    float4 acc0 = make_float4(0.f, 0.f, 0.f, 0.f);
    float4 acc1 = make_float4(0.f, 0.f, 0.f, 0.f);

    int a = 0;
    // Unroll by 4: four independent 512B row reads in flight per warp.
    for (; a + 4 <= cnt; a += 4) {
        float4 v0 = __ldcs(p);
        float4 v1 = __ldcs(p + 32);
        float4 v2 = __ldcs(p + 64);
        float4 v3 = __ldcs(p + 96);
        p += 128;
        acc0.x += v0.x; acc0.y += v0.y; acc0.z += v0.z; acc0.w += v0.w;
        acc1.x += v1.x; acc1.y += v1.y; acc1.z += v1.z; acc1.w += v1.w;
        acc0.x += v2.x; acc0.y += v2.y; acc0.z += v2.z; acc0.w += v2.w;
        acc1.x += v3.x; acc1.y += v3.y; acc1.z += v3.z; acc1.w += v3.w;
    }
    if (a + 2 <= cnt) {
        float4 v0 = __ldcs(p);
        float4 v1 = __ldcs(p + 32);
        p += 64;
        a += 2;
        acc0.x += v0.x; acc0.y += v0.y; acc0.z += v0.z; acc0.w += v0.w;
        acc1.x += v1.x; acc1.y += v1.y; acc1.z += v1.z; acc1.w += v1.w;
    }
    if (a < cnt) {
        float4 v0 = __ldcs(p);
        acc0.x += v0.x; acc0.y += v0.y; acc0.z += v0.z; acc0.w += v0.w;
    }

    float inv = (cnt > 0) ? (1.0f / (float)cnt) : 0.0f;
    float4 r;
    r.x = (acc0.x + acc1.x) * inv;
    r.y = (acc0.y + acc1.y) * inv;
    r.z = (acc0.z + acc1.z) * inv;
    r.w = (acc0.w + acc1.w) * inv;

    __stcs((float4*)(out + (size_t)gwarp * FEAT_DIM) + lane, r);
}

extern "C" void kernel_launch(void* const* d_in, const int* in_sizes, int n_in,
                              void* d_out, int out_size) {
    const float* feat = (const float*)d_in[0];
    const void* idx   = (const void*)d_in[1];
    int n_atoms       = in_sizes[1];

    int threads = 256;
    int work = (n_atoms + IDX_PER_THREAD - 1) / IDX_PER_THREAD;
    int blocks = (work + threads - 1) / threads;
    build_offsets_kernel<<<blocks, threads>>>(idx, n_atoms);

    // 2 warps per block -> 2 residues per block (minimize tail skew)
    int res_per_block = 2;
    int pool_blocks = (NUM_RESIDUES + res_per_block - 1) / res_per_block;
    pool_kernel<<<pool_blocks, 64>>>(feat, (float*)d_out);
}